// round 5
// baseline (speedup 1.0000x reference)
#include <cuda_runtime.h>
#include <math.h>

// ---------------------------------------------------------------------------
// Problem constants (from reference: B=4, N=2048, D=2048, H=16, DK=128, R=32)
// ---------------------------------------------------------------------------
#define B_   4
#define N_   2048
#define D_   2048
#define H_   16
#define DK_  128
#define R_   32
#define M_   (B_ * N_)      // 8192 rows of x
#define HR_  (H_ * R_)      // 512

// ---------------------------------------------------------------------------
// Device scratch (allocation-free rule: __device__ globals)
// ---------------------------------------------------------------------------
__device__ float g_WUq[(size_t)HR_ * D_];                 //  4.2 MB
__device__ float g_WUk[(size_t)HR_ * D_];                 //  4.2 MB
__device__ float g_Q  [(size_t)B_ * H_ * N_ * R_];        // 16.8 MB  [b,h,n,r]
__device__ float g_K  [(size_t)B_ * H_ * N_ * R_];        // 16.8 MB  [b,h,n,r]
__device__ float g_V  [(size_t)B_ * H_ * N_ * DK_];       // 67.1 MB  [b,h,n,dk]
__device__ float g_Z  [(size_t)B_ * N_ * D_];             // 67.1 MB  [b,n,d]

// ---------------------------------------------------------------------------
// Kernel 0: WU[hr, d] = sum_dk W[h*DK+dk, d] * U[dk, r]      (folds U into Wq/Wk)
// grid (D/256, HR), block 256
// ---------------------------------------------------------------------------
__global__ void build_wu_kernel(const float* __restrict__ W,
                                const float* __restrict__ U,
                                float* __restrict__ WU)
{
    int d  = blockIdx.x * 256 + threadIdx.x;   // 0..2047 (coalesced)
    int hr = blockIdx.y;                       // 0..511
    int h  = hr >> 5;
    int r  = hr & 31;
    const float* wcol = W + (size_t)h * DK_ * D_ + d;  // W[(h*DK+dk)*D + d]
    float s = 0.f;
#pragma unroll 8
    for (int dk = 0; dk < DK_; dk++)
        s += wcol[(size_t)dk * D_] * U[dk * R_ + r];
    WU[(size_t)hr * D_ + d] = s;
}

// ---------------------------------------------------------------------------
// Kernel 1: SGEMM  C[m,n] = sum_k A[m,k] * B[n,k]   (both row-major, K-major)
// 128x128 tile, KT=8, 256 threads, 8x8 per thread, register-prefetched gmem.
// MODE 0: plain C[m*NN + n]
// MODE 1: head-split store: b=m/N, t=m%N, h=n/SPLIT, j=n%SPLIT
//         C[((b*H + h)*N + t)*SPLIT + j]
// ---------------------------------------------------------------------------
template <int MODE, int SPLIT>
__global__ void __launch_bounds__(256, 2)
sgemm_tt_kernel(const float* __restrict__ A,
                const float* __restrict__ B,
                float* __restrict__ C,
                int NN, int K)
{
    __shared__ float As[8][128];
    __shared__ float Bs[8][128];

    const int tid = threadIdx.x;
    const int tr  = tid >> 4;     // 0..15 -> row group
    const int tc  = tid & 15;     // 0..15 -> col group
    const int m0  = blockIdx.y * 128;
    const int n0  = blockIdx.x * 128;

    const int lrow  = tid >> 1;   // 0..127
    const int lpart = tid & 1;    // 0..1  (which float4 of the 8-wide k slab)

    const float* Aptr = A + (size_t)(m0 + lrow) * K + lpart * 4;
    const float* Bptr = B + (size_t)(n0 + lrow) * K + lpart * 4;

    float acc[8][8];
#pragma unroll
    for (int i = 0; i < 8; i++)
#pragma unroll
        for (int j = 0; j < 8; j++) acc[i][j] = 0.f;

    // prologue prefetch
    float4 av = *(const float4*)(Aptr);
    float4 bv = *(const float4*)(Bptr);

    for (int k0 = 0; k0 < K; k0 += 8) {
        // stage current tile to smem (transposed: [k][m])
        As[lpart * 4 + 0][lrow] = av.x;
        As[lpart * 4 + 1][lrow] = av.y;
        As[lpart * 4 + 2][lrow] = av.z;
        As[lpart * 4 + 3][lrow] = av.w;
        Bs[lpart * 4 + 0][lrow] = bv.x;
        Bs[lpart * 4 + 1][lrow] = bv.y;
        Bs[lpart * 4 + 2][lrow] = bv.z;
        Bs[lpart * 4 + 3][lrow] = bv.w;
        __syncthreads();

        // prefetch next tile while computing this one
        if (k0 + 8 < K) {
            av = *(const float4*)(Aptr + k0 + 8);
            bv = *(const float4*)(Bptr + k0 + 8);
        }

#pragma unroll
        for (int kk = 0; kk < 8; kk++) {
            float a[8], b[8];
            *(float4*)(a)     = *(const float4*)&As[kk][tr * 8];
            *(float4*)(a + 4) = *(const float4*)&As[kk][tr * 8 + 4];
            *(float4*)(b)     = *(const float4*)&Bs[kk][tc * 8];
            *(float4*)(b + 4) = *(const float4*)&Bs[kk][tc * 8 + 4];
#pragma unroll
            for (int i = 0; i < 8; i++)
#pragma unroll
                for (int j = 0; j < 8; j++)
                    acc[i][j] = fmaf(a[i], b[j], acc[i][j]);
        }
        __syncthreads();
    }

    // epilogue
#pragma unroll
    for (int i = 0; i < 8; i++) {
        int m = m0 + tr * 8 + i;
#pragma unroll
        for (int j = 0; j < 8; j++) {
            int n = n0 + tc * 8 + j;
            if (MODE == 0) {
                C[(size_t)m * NN + n] = acc[i][j];
            } else {
                int b_ = m >> 11;          // m / N_   (N_ = 2048)
                int t  = m & (N_ - 1);
                int h  = n / SPLIT;
                int j2 = n % SPLIT;
                C[(((size_t)(b_ * H_ + h)) * N_ + t) * SPLIT + j2] = acc[i][j];
            }
        }
    }
}

// ---------------------------------------------------------------------------
// Kernel 2: flash attention with ALiBi bias (NOT causal; bias = -slope*max(j-i,0))
//   per CTA: one (b,h) pair, 128 query rows; loops over 16 key tiles of 128.
//   Q,K: [bh, n, 32] ; V: [bh, n, 128] ; Z out: [b, n, h*128 + dk]
// Thread (tr,tc): rows tr*8+i, cols tc+16*j  (conflict-free scalar LDS pattern)
// smem (padded, conflict-free): Qs 128x(33), KsT 32x(129), Vs 128x128, Ps 128x(129)
// ---------------------------------------------------------------------------
#define FL_SMEM_FLOATS (128 * 33 + 32 * 129 + 128 * 128 + 128 * 129)
#define FL_SMEM_BYTES  (FL_SMEM_FLOATS * 4)

__global__ void __launch_bounds__(256, 1)
flash_kernel(const float* __restrict__ Q,
             const float* __restrict__ Kx,
             const float* __restrict__ V,
             float* __restrict__ Z)
{
    extern __shared__ float sm[];
    float* Qs  = sm;                      // 128*33
    float* KsT = Qs + 128 * 33;           // 32*129  (transposed: [kk][key])
    float* Vs  = KsT + 32 * 129;          // 128*128
    float* Ps  = Vs + 128 * 128;          // 128*129

    const int qt  = blockIdx.x;           // query tile 0..15
    const int bh  = blockIdx.y;           // 0..63
    const int h   = bh & (H_ - 1);
    const int b_  = bh >> 4;
    const int q0  = qt * 128;
    const int tid = threadIdx.x;
    const int tr  = tid >> 4;             // 0..15
    const int tc  = tid & 15;             // 0..15

    const float slope = exp2f(-0.5f * (float)(h + 1));   // ALiBi slope, H=16
    const float scale = rsqrtf((float)DK_);

    // load Q tile (pre-scaled by 1/sqrt(DK)); padded stride 33
    const float* Qg = Q + ((size_t)bh * N_ + q0) * R_;
    for (int idx = tid; idx < 128 * 32; idx += 256) {
        int row = idx >> 5, kk = idx & 31;
        Qs[row * 33 + kk] = Qg[idx] * scale;
    }

    const float NEG_INF = -__int_as_float(0x7f800000);
    float m_i[8], l_i[8], o[8][8];
#pragma unroll
    for (int i = 0; i < 8; i++) {
        m_i[i] = NEG_INF;
        l_i[i] = 0.f;
#pragma unroll
        for (int j = 0; j < 8; j++) o[i][j] = 0.f;
    }

    for (int kt = 0; kt < N_ / 128; kt++) {
        const int k0 = kt * 128;

        // load K tile transposed: KsT[kk][key], padded stride 129
        const float* Kg = Kx + ((size_t)bh * N_ + k0) * R_;
        for (int idx = tid; idx < 128 * 32; idx += 256) {
            int row = idx >> 5, kk = idx & 31;
            KsT[kk * 129 + row] = Kg[idx];
        }
        // load V tile flat [key][dk]
        const float* Vg = V + ((size_t)bh * N_ + k0) * DK_;
        for (int idx = tid; idx < 128 * 128; idx += 256)
            Vs[idx] = Vg[idx];
        __syncthreads();

        // S = Q K^T (scaled)  -- 8x8 per thread
        float s[8][8];
#pragma unroll
        for (int i = 0; i < 8; i++)
#pragma unroll
            for (int j = 0; j < 8; j++) s[i][j] = 0.f;

#pragma unroll 8
        for (int kk = 0; kk < 32; kk++) {
            float a[8], bb[8];
#pragma unroll
            for (int i = 0; i < 8; i++) a[i] = Qs[(tr * 8 + i) * 33 + kk];
#pragma unroll
            for (int j = 0; j < 8; j++) bb[j] = KsT[kk * 129 + tc + 16 * j];
#pragma unroll
            for (int i = 0; i < 8; i++)
#pragma unroll
                for (int j = 0; j < 8; j++)
                    s[i][j] = fmaf(a[i], bb[j], s[i][j]);
        }

        // bias + online softmax (row stats reduced across the 16 tc lanes)
#pragma unroll
        for (int i = 0; i < 8; i++) {
            const int ig = q0 + tr * 8 + i;
            float tmax = NEG_INF;
#pragma unroll
            for (int j = 0; j < 8; j++) {
                int jg = k0 + tc + 16 * j;
                float d = (float)(jg - ig);
                s[i][j] -= slope * fmaxf(d, 0.f);
                tmax = fmaxf(tmax, s[i][j]);
            }
#pragma unroll
            for (int off = 8; off >= 1; off >>= 1)
                tmax = fmaxf(tmax, __shfl_xor_sync(0xffffffffu, tmax, off));

            float mnew  = fmaxf(m_i[i], tmax);
            float alpha = __expf(m_i[i] - mnew);   // exp(-inf)=0 on first tile
            float rsum  = 0.f;
#pragma unroll
            for (int j = 0; j < 8; j++) {
                float p = __expf(s[i][j] - mnew);
                s[i][j] = p;
                rsum += p;
            }
#pragma unroll
            for (int off = 8; off >= 1; off >>= 1)
                rsum += __shfl_xor_sync(0xffffffffu, rsum, off);

            l_i[i] = l_i[i] * alpha + rsum;
            m_i[i] = mnew;
#pragma unroll
            for (int j = 0; j < 8; j++) o[i][j] *= alpha;
            // stage P (padded stride 129)
#pragma unroll
            for (int j = 0; j < 8; j++)
                Ps[(tr * 8 + i) * 129 + tc + 16 * j] = s[i][j];
        }
        __syncthreads();

        // O += P @ V
#pragma unroll 4
        for (int k = 0; k < 128; k++) {
            float p[8], v[8];
#pragma unroll
            for (int i = 0; i < 8; i++) p[i] = Ps[(tr * 8 + i) * 129 + k];
#pragma unroll
            for (int j = 0; j < 8; j++) v[j] = Vs[k * 128 + tc + 16 * j];
#pragma unroll
            for (int i = 0; i < 8; i++)
#pragma unroll
                for (int j = 0; j < 8; j++)
                    o[i][j] = fmaf(p[i], v[j], o[i][j]);
        }
        __syncthreads();
    }

    // finalize: Z[b, q, h*128 + dk] = O / l
#pragma unroll
    for (int i = 0; i < 8; i++) {
        float inv = 1.f / l_i[i];
        size_t zrow = ((size_t)b_ * N_ + q0 + tr * 8 + i) * D_ + h * DK_;
#pragma unroll
        for (int j = 0; j < 8; j++)
            Z[zrow + tc + 16 * j] = o[i][j] * inv;
    }
}

// ---------------------------------------------------------------------------
// Host launcher (graph-capturable: kernel launches only, default stream)
// ---------------------------------------------------------------------------
extern "C" void kernel_launch(void* const* d_in, const int* in_sizes, int n_in,
                              void* d_out, int out_size)
{
    (void)in_sizes; (void)n_in; (void)out_size;
    const float* x     = (const float*)d_in[0];
    const float* Wq    = (const float*)d_in[1];
    const float* Wk    = (const float*)d_in[2];
    const float* Wv    = (const float*)d_in[3];
    const float* U     = (const float*)d_in[4];
    const float* Wproj = (const float*)d_in[5];
    float* out = (float*)d_out;

    float *WUq, *WUk, *Qp, *Kp, *Vp, *Zp;
    cudaGetSymbolAddress((void**)&WUq, g_WUq);
    cudaGetSymbolAddress((void**)&WUk, g_WUk);
    cudaGetSymbolAddress((void**)&Qp,  g_Q);
    cudaGetSymbolAddress((void**)&Kp,  g_K);
    cudaGetSymbolAddress((void**)&Vp,  g_V);
    cudaGetSymbolAddress((void**)&Zp,  g_Z);

    // opt-in to >48KB dynamic smem for the flash kernel (sticky per-function;
    // first set happens on the pre-capture correctness call)
    cudaFuncSetAttribute(flash_kernel,
                         cudaFuncAttributeMaxDynamicSharedMemorySize,
                         FL_SMEM_BYTES);

    // 0) fold U into Wq / Wk:  WU [512, 2048]
    build_wu_kernel<<<dim3(D_ / 256, HR_), 256>>>(Wq, U, WUq);
    build_wu_kernel<<<dim3(D_ / 256, HR_), 256>>>(Wk, U, WUk);

    // 1) Q = x @ WUq^T   -> [b,h,n,r]       (M=8192, NN=512, K=2048)
    sgemm_tt_kernel<1, R_><<<dim3(HR_ / 128, M_ / 128), 256>>>(x, WUq, Qp, HR_, D_);
    // 2) K = x @ WUk^T   -> [b,h,n,r]
    sgemm_tt_kernel<1, R_><<<dim3(HR_ / 128, M_ / 128), 256>>>(x, WUk, Kp, HR_, D_);
    // 3) V = x @ Wv^T    -> [b,h,n,dk]      (M=8192, NN=2048, K=2048)
    sgemm_tt_kernel<1, DK_><<<dim3(D_ / 128, M_ / 128), 256>>>(x, Wv, Vp, D_, D_);

    // 4) flash attention with ALiBi -> Z [b,n,d]
    flash_kernel<<<dim3(N_ / 128, B_ * H_), 256, FL_SMEM_BYTES>>>(Qp, Kp, Vp, Zp);

    // 5) out = Z @ Wproj^T                   (M=8192, NN=2048, K=2048)
    sgemm_tt_kernel<0, 1><<<dim3(D_ / 128, M_ / 128), 256>>>(Zp, Wproj, out, D_, D_);
}

// round 7
// speedup vs baseline: 1.5180x; 1.5180x over previous
#include <cuda_runtime.h>
#include <cuda_bf16.h>
#include <math.h>
#include <stdint.h>

// ---------------------------------------------------------------------------
// Problem constants (B=4, N=2048, D=2048, H=16, DK=128, R=32)
// ---------------------------------------------------------------------------
#define B_   4
#define N_   2048
#define D_   2048
#define H_   16
#define DK_  128
#define R_   32
#define M_   (B_ * N_)      // 8192
#define HR_  (H_ * R_)      // 512

// ---------------------------------------------------------------------------
// Device scratch
// ---------------------------------------------------------------------------
__device__ float g_WUq[(size_t)HR_ * D_];
__device__ float g_WUk[(size_t)HR_ * D_];
__device__ float g_Q  [(size_t)B_ * H_ * N_ * R_];     // [b,h,n,r]
__device__ float g_K  [(size_t)B_ * H_ * N_ * R_];
__device__ float g_V  [(size_t)B_ * H_ * N_ * DK_];    // [b,h,n,dk]
__device__ float g_Z  [(size_t)B_ * N_ * D_];          // [b,n,d]

// ---------------------------------------------------------------------------
// mma / ldmatrix wrappers (sm_80-era PTX; supported on plain sm_103 target)
// ---------------------------------------------------------------------------
__device__ __forceinline__ uint32_t smem_u32(const void* p) {
    uint32_t a;
    asm("{ .reg .u64 t; cvta.to.shared.u64 t, %1; cvt.u32.u64 %0, t; }"
        : "=r"(a) : "l"(p));
    return a;
}

__device__ __forceinline__ void ldsm_x4(uint32_t* r, uint32_t addr) {
    asm volatile("ldmatrix.sync.aligned.m8n8.x4.shared.b16 {%0,%1,%2,%3}, [%4];"
                 : "=r"(r[0]), "=r"(r[1]), "=r"(r[2]), "=r"(r[3]) : "r"(addr));
}
__device__ __forceinline__ void ldsm_x2(uint32_t* r, uint32_t addr) {
    asm volatile("ldmatrix.sync.aligned.m8n8.x2.shared.b16 {%0,%1}, [%2];"
                 : "=r"(r[0]), "=r"(r[1]) : "r"(addr));
}
__device__ __forceinline__ void mma_bf16(float* d, const uint32_t* a, const uint32_t* b) {
    asm volatile(
        "mma.sync.aligned.m16n8k16.row.col.f32.bf16.bf16.f32 "
        "{%0,%1,%2,%3}, {%4,%5,%6,%7}, {%8,%9}, {%0,%1,%2,%3};"
        : "+f"(d[0]), "+f"(d[1]), "+f"(d[2]), "+f"(d[3])
        : "r"(a[0]), "r"(a[1]), "r"(a[2]), "r"(a[3]), "r"(b[0]), "r"(b[1]));
}

// ---------------------------------------------------------------------------
// Kernel 0: WU[hr, d] = sum_dk W[h*DK+dk, d] * U[dk, r]   (fp32 out)
// ---------------------------------------------------------------------------
__global__ void build_wu_kernel(const float* __restrict__ W,
                                const float* __restrict__ U,
                                float* __restrict__ WU)
{
    int d  = blockIdx.x * 256 + threadIdx.x;
    int hr = blockIdx.y;
    int h  = hr >> 5;
    int r  = hr & 31;
    const float* wcol = W + (size_t)h * DK_ * D_ + d;
    float s = 0.f;
#pragma unroll 8
    for (int dk = 0; dk < DK_; dk++)
        s += wcol[(size_t)dk * D_] * U[dk * R_ + r];
    WU[(size_t)hr * D_ + d] = s;
}

// ---------------------------------------------------------------------------
// Kernel 1: HMMA 3xBF16 split-precision GEMM
//   C[m,n] = sum_k A[m,k]*B[n,k]; A,B fp32 (K-major); converted to bf16 hi/lo
//   on the fly during tile load (same gmem bytes as pre-split bf16).
// CTA: 128x128, BK=32, 256 threads (8 warps as 2(M) x 4(N), warp tile 64x32).
// smem: Ah/Al/Bh/Bl, each [128][40] bf16 (row pad -> conflict-free ldmatrix).
// MODE 0: C[m*NN + n]
// MODE 1: C[((b*H + n/SPLIT)*N + m%N)*SPLIT + n%SPLIT], b = m/N_
// ---------------------------------------------------------------------------
#define GM_AH 0
#define GM_AL 10240
#define GM_BH 20480
#define GM_BL 30720
#define GM_SMEM 40960

__device__ __forceinline__ void split2(float x, __nv_bfloat16& h, __nv_bfloat16& l) {
    h = __float2bfloat16(x);
    l = __float2bfloat16(x - __bfloat162float(h));
}
__device__ __forceinline__ uint32_t packbf(__nv_bfloat16 a, __nv_bfloat16 b) {
    return (uint32_t)__bfloat16_as_ushort(a) | ((uint32_t)__bfloat16_as_ushort(b) << 16);
}

template <int MODE, int SPLIT>
__global__ void __launch_bounds__(256, 2)
gemm_mma_bf16x3(const float* __restrict__ A,
                const float* __restrict__ B,
                float* __restrict__ C, int NN, int K)
{
    extern __shared__ char sm[];
    const uint32_t sb = smem_u32(sm);

    const int tid  = threadIdx.x;
    const int lane = tid & 31;
    const int wid  = tid >> 5;
    const int wm   = wid & 1;      // 0..1  (64 rows each)
    const int wn   = wid >> 1;     // 0..3  (32 cols each)
    const int m0   = blockIdx.y * 128;
    const int n0   = blockIdx.x * 128;

    float acc[4][4][4];
#pragma unroll
    for (int mi = 0; mi < 4; mi++)
#pragma unroll
        for (int ni = 0; ni < 4; ni++)
#pragma unroll
            for (int f = 0; f < 4; f++) acc[mi][ni][f] = 0.f;

    // ldmatrix per-thread base addresses (bytes); row stride 40 bf16 = 80 B
    const uint32_t a_addr = sb + GM_AH +
        (uint32_t)((wm * 64 + (lane & 15)) * 40 + ((lane >> 4) * 8)) * 2;
    const uint32_t b_addr = sb + GM_BH +
        (uint32_t)((wn * 32 + (lane & 7)) * 40 + (((lane >> 3) & 1) * 8)) * 2;

    // gmem load coords: 1024 16B-chunks per tile, 4 per thread
    const int lr = tid >> 3;        // base row within tile for v=0 (0..31)
    const int lq = tid & 7;         // float4 index within 32-float row slab

    const int niter = K / 32;
    for (int it = 0; it < niter; ++it) {
        // ---- prefetch fp32 tiles to regs ----
        float4 a4[4], b4[4];
#pragma unroll
        for (int v = 0; v < 4; v++) {
            int r = lr + v * 32;
            a4[v] = *(const float4*)(A + (size_t)(m0 + r) * K + it * 32 + lq * 4);
            b4[v] = *(const float4*)(B + (size_t)(n0 + r) * K + it * 32 + lq * 4);
        }
        __syncthreads();   // previous iteration's MMAs have consumed smem

        // ---- convert to bf16 hi/lo and store (8B per store, 8B aligned) ----
#pragma unroll
        for (int v = 0; v < 4; v++) {
            int r = lr + v * 32;
            uint32_t off = (uint32_t)(r * 80 + lq * 8);
            __nv_bfloat16 h0, h1, h2, h3, l0, l1, l2, l3;
            split2(a4[v].x, h0, l0); split2(a4[v].y, h1, l1);
            split2(a4[v].z, h2, l2); split2(a4[v].w, h3, l3);
            *(uint2*)(sm + GM_AH + off) = make_uint2(packbf(h0, h1), packbf(h2, h3));
            *(uint2*)(sm + GM_AL + off) = make_uint2(packbf(l0, l1), packbf(l2, l3));
            split2(b4[v].x, h0, l0); split2(b4[v].y, h1, l1);
            split2(b4[v].z, h2, l2); split2(b4[v].w, h3, l3);
            *(uint2*)(sm + GM_BH + off) = make_uint2(packbf(h0, h1), packbf(h2, h3));
            *(uint2*)(sm + GM_BL + off) = make_uint2(packbf(l0, l1), packbf(l2, l3));
        }
        __syncthreads();

        // ---- 2 x k16 MMA steps ----
#pragma unroll
        for (int ks = 0; ks < 2; ks++) {
            uint32_t ah[4][4], al[4][4];
#pragma unroll
            for (int mi = 0; mi < 4; mi++) {
                uint32_t off = (uint32_t)(mi * 1280 + ks * 32);   // mi*16rows*80B + ks*16col*2B
                ldsm_x4(ah[mi], a_addr + off);
                ldsm_x4(al[mi], a_addr + off + (GM_AL - GM_AH));
            }
#pragma unroll
            for (int ni = 0; ni < 4; ni++) {
                uint32_t bh[2], bl[2];
                uint32_t off = (uint32_t)(ni * 640 + ks * 32);    // ni*8rows*80B
                ldsm_x2(bh, b_addr + off);
                ldsm_x2(bl, b_addr + off + (GM_BL - GM_BH));
#pragma unroll
                for (int mi = 0; mi < 4; mi++) {
                    mma_bf16(acc[mi][ni], ah[mi], bh);
                    mma_bf16(acc[mi][ni], ah[mi], bl);
                    mma_bf16(acc[mi][ni], al[mi], bh);
                }
            }
        }
    }

    // ---- epilogue: fragment-direct stores (pairs are contiguous in n) ----
    const int g  = lane >> 2;        // 0..7
    const int c2 = (lane & 3) * 2;   // 0,2,4,6
#pragma unroll
    for (int mi = 0; mi < 4; mi++) {
#pragma unroll
        for (int ni = 0; ni < 4; ni++) {
            int m = m0 + wm * 64 + mi * 16 + g;
            int n = n0 + wn * 32 + ni * 8 + c2;
#pragma unroll
            for (int half = 0; half < 2; half++) {
                int mm = m + half * 8;
                float2 val = make_float2(acc[mi][ni][half * 2], acc[mi][ni][half * 2 + 1]);
                if (MODE == 0) {
                    *(float2*)(C + (size_t)mm * NN + n) = val;
                } else {
                    int b_ = mm >> 11;            // mm / N_
                    int t  = mm & (N_ - 1);
                    int h  = n / SPLIT;
                    int j  = n % SPLIT;
                    *(float2*)(C + (((size_t)(b_ * H_ + h)) * N_ + t) * SPLIT + j) = val;
                }
            }
        }
    }
}

// ---------------------------------------------------------------------------
// Kernel 2: flash attention with ALiBi bias (unchanged; rel_err 1.6e-6 proven)
// ---------------------------------------------------------------------------
#define FL_SMEM_FLOATS (128 * 33 + 32 * 129 + 128 * 128 + 128 * 129)
#define FL_SMEM_BYTES  (FL_SMEM_FLOATS * 4)

__global__ void __launch_bounds__(256, 1)
flash_kernel(const float* __restrict__ Q,
             const float* __restrict__ Kx,
             const float* __restrict__ V,
             float* __restrict__ Z)
{
    extern __shared__ float smf[];
    float* Qs  = smf;                     // 128*33
    float* KsT = Qs + 128 * 33;           // 32*129
    float* Vs  = KsT + 32 * 129;          // 128*128
    float* Ps  = Vs + 128 * 128;          // 128*129

    const int qt  = blockIdx.x;
    const int bh  = blockIdx.y;
    const int h   = bh & (H_ - 1);
    const int b_  = bh >> 4;
    const int q0  = qt * 128;
    const int tid = threadIdx.x;
    const int tr  = tid >> 4;
    const int tc  = tid & 15;

    const float slope = exp2f(-0.5f * (float)(h + 1));
    const float scale = rsqrtf((float)DK_);

    const float* Qg = Q + ((size_t)bh * N_ + q0) * R_;
    for (int idx = tid; idx < 128 * 32; idx += 256) {
        int row = idx >> 5, kk = idx & 31;
        Qs[row * 33 + kk] = Qg[idx] * scale;
    }

    const float NEG_INF = -__int_as_float(0x7f800000);
    float m_i[8], l_i[8], o[8][8];
#pragma unroll
    for (int i = 0; i < 8; i++) {
        m_i[i] = NEG_INF; l_i[i] = 0.f;
#pragma unroll
        for (int j = 0; j < 8; j++) o[i][j] = 0.f;
    }

    for (int kt = 0; kt < N_ / 128; kt++) {
        const int k0 = kt * 128;
        const float* Kg = Kx + ((size_t)bh * N_ + k0) * R_;
        for (int idx = tid; idx < 128 * 32; idx += 256) {
            int row = idx >> 5, kk = idx & 31;
            KsT[kk * 129 + row] = Kg[idx];
        }
        const float* Vg = V + ((size_t)bh * N_ + k0) * DK_;
        for (int idx = tid; idx < 128 * 128; idx += 256)
            Vs[idx] = Vg[idx];
        __syncthreads();

        float s[8][8];
#pragma unroll
        for (int i = 0; i < 8; i++)
#pragma unroll
            for (int j = 0; j < 8; j++) s[i][j] = 0.f;

#pragma unroll 8
        for (int kk = 0; kk < 32; kk++) {
            float a[8], bb[8];
#pragma unroll
            for (int i = 0; i < 8; i++) a[i] = Qs[(tr * 8 + i) * 33 + kk];
#pragma unroll
            for (int j = 0; j < 8; j++) bb[j] = KsT[kk * 129 + tc + 16 * j];
#pragma unroll
            for (int i = 0; i < 8; i++)
#pragma unroll
                for (int j = 0; j < 8; j++)
                    s[i][j] = fmaf(a[i], bb[j], s[i][j]);
        }

#pragma unroll
        for (int i = 0; i < 8; i++) {
            const int ig = q0 + tr * 8 + i;
            float tmax = NEG_INF;
#pragma unroll
            for (int j = 0; j < 8; j++) {
                int jg = k0 + tc + 16 * j;
                float d = (float)(jg - ig);
                s[i][j] -= slope * fmaxf(d, 0.f);
                tmax = fmaxf(tmax, s[i][j]);
            }
#pragma unroll
            for (int off = 8; off >= 1; off >>= 1)
                tmax = fmaxf(tmax, __shfl_xor_sync(0xffffffffu, tmax, off));

            float mnew  = fmaxf(m_i[i], tmax);
            float alpha = __expf(m_i[i] - mnew);
            float rsum  = 0.f;
#pragma unroll
            for (int j = 0; j < 8; j++) {
                float p = __expf(s[i][j] - mnew);
                s[i][j] = p;
                rsum += p;
            }
#pragma unroll
            for (int off = 8; off >= 1; off >>= 1)
                rsum += __shfl_xor_sync(0xffffffffu, rsum, off);

            l_i[i] = l_i[i] * alpha + rsum;
            m_i[i] = mnew;
#pragma unroll
            for (int j = 0; j < 8; j++) o[i][j] *= alpha;
#pragma unroll
            for (int j = 0; j < 8; j++)
                Ps[(tr * 8 + i) * 129 + tc + 16 * j] = s[i][j];
        }
        __syncthreads();

#pragma unroll 4
        for (int k = 0; k < 128; k++) {
            float p[8], v[8];
#pragma unroll
            for (int i = 0; i < 8; i++) p[i] = Ps[(tr * 8 + i) * 129 + k];
#pragma unroll
            for (int j = 0; j < 8; j++) v[j] = Vs[k * 128 + tc + 16 * j];
#pragma unroll
            for (int i = 0; i < 8; i++)
#pragma unroll
                for (int j = 0; j < 8; j++)
                    o[i][j] = fmaf(p[i], v[j], o[i][j]);
        }
        __syncthreads();
    }

#pragma unroll
    for (int i = 0; i < 8; i++) {
        float inv = 1.f / l_i[i];
        size_t zrow = ((size_t)b_ * N_ + q0 + tr * 8 + i) * D_ + h * DK_;
#pragma unroll
        for (int j = 0; j < 8; j++)
            Z[zrow + tc + 16 * j] = o[i][j] * inv;
    }
}

// ---------------------------------------------------------------------------
// Host launcher (graph-capturable: kernel launches only)
// ---------------------------------------------------------------------------
extern "C" void kernel_launch(void* const* d_in, const int* in_sizes, int n_in,
                              void* d_out, int out_size)
{
    (void)in_sizes; (void)n_in; (void)out_size;
    const float* x     = (const float*)d_in[0];
    const float* Wq    = (const float*)d_in[1];
    const float* Wk    = (const float*)d_in[2];
    const float* Wv    = (const float*)d_in[3];
    const float* U     = (const float*)d_in[4];
    const float* Wproj = (const float*)d_in[5];
    float* out = (float*)d_out;

    float *WUq, *WUk, *Qp, *Kp, *Vp, *Zp;
    cudaGetSymbolAddress((void**)&WUq, g_WUq);
    cudaGetSymbolAddress((void**)&WUk, g_WUk);
    cudaGetSymbolAddress((void**)&Qp,  g_Q);
    cudaGetSymbolAddress((void**)&Kp,  g_K);
    cudaGetSymbolAddress((void**)&Vp,  g_V);
    cudaGetSymbolAddress((void**)&Zp,  g_Z);

    cudaFuncSetAttribute(flash_kernel,
                         cudaFuncAttributeMaxDynamicSharedMemorySize, FL_SMEM_BYTES);

    // 0) fold U into Wq/Wk (fp32)
    build_wu_kernel<<<dim3(D_ / 256, HR_), 256>>>(Wq, U, WUq);
    build_wu_kernel<<<dim3(D_ / 256, HR_), 256>>>(Wk, U, WUk);

    // 1) Q = x @ WUq^T  -> [b,h,n,r]        (NN=512)
    gemm_mma_bf16x3<1, R_><<<dim3(HR_ / 128, M_ / 128), 256, GM_SMEM>>>(
        x, WUq, Qp, HR_, D_);
    // 2) K = x @ WUk^T
    gemm_mma_bf16x3<1, R_><<<dim3(HR_ / 128, M_ / 128), 256, GM_SMEM>>>(
        x, WUk, Kp, HR_, D_);
    // 3) V = x @ Wv^T   -> [b,h,n,dk]       (NN=2048)
    gemm_mma_bf16x3<1, DK_><<<dim3(D_ / 128, M_ / 128), 256, GM_SMEM>>>(
        x, Wv, Vp, D_, D_);

    // 4) flash attention with ALiBi -> Z [b,n,d]
    flash_kernel<<<dim3(N_ / 128, B_ * H_), 256, FL_SMEM_BYTES>>>(Qp, Kp, Vp, Zp);

    // 5) out = Z @ Wproj^T
    gemm_mma_bf16x3<0, 1><<<dim3(D_ / 128, M_ / 128), 256, GM_SMEM>>>(
        Zp, Wproj, out, D_, D_);
}

// round 8
// speedup vs baseline: 2.9089x; 1.9162x over previous
#include <cuda_runtime.h>
#include <cuda_bf16.h>
#include <math.h>
#include <stdint.h>

// ---------------------------------------------------------------------------
// Problem constants (B=4, N=2048, D=2048, H=16, DK=128, R=32)
// ---------------------------------------------------------------------------
#define B_   4
#define N_   2048
#define D_   2048
#define H_   16
#define DK_  128
#define R_   32
#define M_   (B_ * N_)      // 8192
#define HR_  (H_ * R_)      // 512

// ---------------------------------------------------------------------------
// Device scratch
// ---------------------------------------------------------------------------
__device__ float g_WUq[(size_t)HR_ * D_];
__device__ float g_WUk[(size_t)HR_ * D_];
__device__ float g_Q  [(size_t)B_ * H_ * N_ * R_];     // [b,h,n,r]
__device__ float g_K  [(size_t)B_ * H_ * N_ * R_];
__device__ float g_V  [(size_t)B_ * H_ * N_ * DK_];    // [b,h,n,dk]
__device__ float g_Z  [(size_t)B_ * N_ * D_];          // [b,n,d]

// ---------------------------------------------------------------------------
// mma / ldmatrix wrappers (sm_80-era PTX; supported on plain sm_103 target)
// ---------------------------------------------------------------------------
__device__ __forceinline__ uint32_t smem_u32(const void* p) {
    uint32_t a;
    asm("{ .reg .u64 t; cvta.to.shared.u64 t, %1; cvt.u32.u64 %0, t; }"
        : "=r"(a) : "l"(p));
    return a;
}

__device__ __forceinline__ void ldsm_x4(uint32_t* r, uint32_t addr) {
    asm volatile("ldmatrix.sync.aligned.m8n8.x4.shared.b16 {%0,%1,%2,%3}, [%4];"
                 : "=r"(r[0]), "=r"(r[1]), "=r"(r[2]), "=r"(r[3]) : "r"(addr));
}
__device__ __forceinline__ void ldsm_x2(uint32_t* r, uint32_t addr) {
    asm volatile("ldmatrix.sync.aligned.m8n8.x2.shared.b16 {%0,%1}, [%2];"
                 : "=r"(r[0]), "=r"(r[1]) : "r"(addr));
}
__device__ __forceinline__ void ldsm_x4_t(uint32_t* r, uint32_t addr) {
    asm volatile("ldmatrix.sync.aligned.m8n8.x4.trans.shared.b16 {%0,%1,%2,%3}, [%4];"
                 : "=r"(r[0]), "=r"(r[1]), "=r"(r[2]), "=r"(r[3]) : "r"(addr));
}
__device__ __forceinline__ void mma_bf16(float* d, const uint32_t* a, const uint32_t* b) {
    asm volatile(
        "mma.sync.aligned.m16n8k16.row.col.f32.bf16.bf16.f32 "
        "{%0,%1,%2,%3}, {%4,%5,%6,%7}, {%8,%9}, {%0,%1,%2,%3};"
        : "+f"(d[0]), "+f"(d[1]), "+f"(d[2]), "+f"(d[3])
        : "r"(a[0]), "r"(a[1]), "r"(a[2]), "r"(a[3]), "r"(b[0]), "r"(b[1]));
}

__device__ __forceinline__ void split2(float x, __nv_bfloat16& h, __nv_bfloat16& l) {
    h = __float2bfloat16(x);
    l = __float2bfloat16(x - __bfloat162float(h));
}
__device__ __forceinline__ uint32_t packbf(__nv_bfloat16 a, __nv_bfloat16 b) {
    return (uint32_t)__bfloat16_as_ushort(a) | ((uint32_t)__bfloat16_as_ushort(b) << 16);
}
__device__ __forceinline__ void pack_hilo(float x, float y, uint32_t& hi, uint32_t& lo) {
    __nv_bfloat16 hx, lx, hy, ly;
    split2(x, hx, lx); split2(y, hy, ly);
    hi = packbf(hx, hy); lo = packbf(lx, ly);
}

// ---------------------------------------------------------------------------
// Kernel 0: WU[hr, d] = sum_dk W[h*DK+dk, d] * U[dk, r]   (fp32 out)
// ---------------------------------------------------------------------------
__global__ void build_wu_kernel(const float* __restrict__ W,
                                const float* __restrict__ U,
                                float* __restrict__ WU)
{
    int d  = blockIdx.x * 256 + threadIdx.x;
    int hr = blockIdx.y;
    int h  = hr >> 5;
    int r  = hr & 31;
    const float* wcol = W + (size_t)h * DK_ * D_ + d;
    float s = 0.f;
#pragma unroll 8
    for (int dk = 0; dk < DK_; dk++)
        s += wcol[(size_t)dk * D_] * U[dk * R_ + r];
    WU[(size_t)hr * D_ + d] = s;
}

// ---------------------------------------------------------------------------
// Kernel 1: HMMA 3xBF16 split-precision GEMM (unchanged from R7; proven)
// ---------------------------------------------------------------------------
#define GM_AH 0
#define GM_AL 10240
#define GM_BH 20480
#define GM_BL 30720
#define GM_SMEM 40960

template <int MODE, int SPLIT>
__global__ void __launch_bounds__(256, 2)
gemm_mma_bf16x3(const float* __restrict__ A,
                const float* __restrict__ B,
                float* __restrict__ C, int NN, int K)
{
    extern __shared__ char sm[];
    const uint32_t sb = smem_u32(sm);

    const int tid  = threadIdx.x;
    const int lane = tid & 31;
    const int wid  = tid >> 5;
    const int wm   = wid & 1;
    const int wn   = wid >> 1;
    const int m0   = blockIdx.y * 128;
    const int n0   = blockIdx.x * 128;

    float acc[4][4][4];
#pragma unroll
    for (int mi = 0; mi < 4; mi++)
#pragma unroll
        for (int ni = 0; ni < 4; ni++)
#pragma unroll
            for (int f = 0; f < 4; f++) acc[mi][ni][f] = 0.f;

    const uint32_t a_addr = sb + GM_AH +
        (uint32_t)((wm * 64 + (lane & 15)) * 40 + ((lane >> 4) * 8)) * 2;
    const uint32_t b_addr = sb + GM_BH +
        (uint32_t)((wn * 32 + (lane & 7)) * 40 + (((lane >> 3) & 1) * 8)) * 2;

    const int lr = tid >> 3;
    const int lq = tid & 7;

    const int niter = K / 32;
    for (int it = 0; it < niter; ++it) {
        float4 a4[4], b4[4];
#pragma unroll
        for (int v = 0; v < 4; v++) {
            int r = lr + v * 32;
            a4[v] = *(const float4*)(A + (size_t)(m0 + r) * K + it * 32 + lq * 4);
            b4[v] = *(const float4*)(B + (size_t)(n0 + r) * K + it * 32 + lq * 4);
        }
        __syncthreads();

#pragma unroll
        for (int v = 0; v < 4; v++) {
            int r = lr + v * 32;
            uint32_t off = (uint32_t)(r * 80 + lq * 8);
            __nv_bfloat16 h0, h1, h2, h3, l0, l1, l2, l3;
            split2(a4[v].x, h0, l0); split2(a4[v].y, h1, l1);
            split2(a4[v].z, h2, l2); split2(a4[v].w, h3, l3);
            *(uint2*)(sm + GM_AH + off) = make_uint2(packbf(h0, h1), packbf(h2, h3));
            *(uint2*)(sm + GM_AL + off) = make_uint2(packbf(l0, l1), packbf(l2, l3));
            split2(b4[v].x, h0, l0); split2(b4[v].y, h1, l1);
            split2(b4[v].z, h2, l2); split2(b4[v].w, h3, l3);
            *(uint2*)(sm + GM_BH + off) = make_uint2(packbf(h0, h1), packbf(h2, h3));
            *(uint2*)(sm + GM_BL + off) = make_uint2(packbf(l0, l1), packbf(l2, l3));
        }
        __syncthreads();

#pragma unroll
        for (int ks = 0; ks < 2; ks++) {
            uint32_t ah[4][4], al[4][4];
#pragma unroll
            for (int mi = 0; mi < 4; mi++) {
                uint32_t off = (uint32_t)(mi * 1280 + ks * 32);
                ldsm_x4(ah[mi], a_addr + off);
                ldsm_x4(al[mi], a_addr + off + (GM_AL - GM_AH));
            }
#pragma unroll
            for (int ni = 0; ni < 4; ni++) {
                uint32_t bh[2], bl[2];
                uint32_t off = (uint32_t)(ni * 640 + ks * 32);
                ldsm_x2(bh, b_addr + off);
                ldsm_x2(bl, b_addr + off + (GM_BL - GM_BH));
#pragma unroll
                for (int mi = 0; mi < 4; mi++) {
                    mma_bf16(acc[mi][ni], ah[mi], bh);
                    mma_bf16(acc[mi][ni], ah[mi], bl);
                    mma_bf16(acc[mi][ni], al[mi], bh);
                }
            }
        }
    }

    const int g  = lane >> 2;
    const int c2 = (lane & 3) * 2;
#pragma unroll
    for (int mi = 0; mi < 4; mi++) {
#pragma unroll
        for (int ni = 0; ni < 4; ni++) {
            int m = m0 + wm * 64 + mi * 16 + g;
            int n = n0 + wn * 32 + ni * 8 + c2;
#pragma unroll
            for (int half = 0; half < 2; half++) {
                int mm = m + half * 8;
                float2 val = make_float2(acc[mi][ni][half * 2], acc[mi][ni][half * 2 + 1]);
                if (MODE == 0) {
                    *(float2*)(C + (size_t)mm * NN + n) = val;
                } else {
                    int b_ = mm >> 11;
                    int t  = mm & (N_ - 1);
                    int h  = n / SPLIT;
                    int j  = n % SPLIT;
                    *(float2*)(C + (((size_t)(b_ * H_ + h)) * N_ + t) * SPLIT + j) = val;
                }
            }
        }
    }
}

// ---------------------------------------------------------------------------
// Kernel 2: HMMA flash attention with ALiBi (3xBF16 split on both GEMMs)
//   CTA: 128 q-rows, 8 warps (16 q-rows each), loops 16 key tiles of 128.
//   Q frags live in registers; P packed register-to-register (C-frag == A-frag
//   layout); V B-frags via ldmatrix.trans from [key][dk] smem.
// smem: QH/QL 128x40bf16 (80B rows), KH/KL same, VH/VL 128x136bf16 (272B rows)
// ---------------------------------------------------------------------------
#define FLM_QH 0
#define FLM_QL 10240
#define FLM_KH 20480
#define FLM_KL 30720
#define FLM_VH 40960
#define FLM_VL 75776
#define FLM_SMEM 110592
#define VSTR 272

__global__ void __launch_bounds__(256, 1)
flash_mma_kernel(const float* __restrict__ Q,
                 const float* __restrict__ Kx,
                 const float* __restrict__ V,
                 float* __restrict__ Z)
{
    extern __shared__ char sm[];
    const uint32_t sb = smem_u32(sm);

    const int tid  = threadIdx.x;
    const int lane = tid & 31;
    const int wq   = tid >> 5;            // warp 0..7 -> q rows wq*16..+15
    const int bh   = blockIdx.y;
    const int h    = bh & (H_ - 1);
    const int b_   = bh >> 4;
    const int q0   = blockIdx.x * 128;
    const int g    = lane >> 2;           // 0..7
    const int t4   = lane & 3;            // 0..3

    const float slope = exp2f(-0.5f * (float)(h + 1));
    const float scale = rsqrtf((float)DK_);
    const float NEG_INF = -__int_as_float(0x7f800000);

    // ---- load Q tile (scaled), split to bf16 hi/lo smem ----
    {
        const float* Qg = Q + ((size_t)bh * N_ + q0) * R_;
#pragma unroll
        for (int v = 0; v < 4; v++) {
            int c = tid + v * 256;
            int r = c >> 3, q = c & 7;
            float4 f = *(const float4*)(Qg + (size_t)r * R_ + q * 4);
            f.x *= scale; f.y *= scale; f.z *= scale; f.w *= scale;
            __nv_bfloat16 h0, h1, h2, h3, l0, l1, l2, l3;
            split2(f.x, h0, l0); split2(f.y, h1, l1);
            split2(f.z, h2, l2); split2(f.w, h3, l3);
            uint32_t off = (uint32_t)(r * 80 + q * 8);
            *(uint2*)(sm + FLM_QH + off) = make_uint2(packbf(h0, h1), packbf(h2, h3));
            *(uint2*)(sm + FLM_QL + off) = make_uint2(packbf(l0, l1), packbf(l2, l3));
        }
    }
    __syncthreads();

    // ---- Q fragments (held in regs for whole kernel) ----
    uint32_t qh[2][4], ql[2][4];
    {
        uint32_t qaddr = sb + FLM_QH +
            (uint32_t)((wq * 16 + (lane & 15)) * 40 + (lane >> 4) * 8) * 2;
#pragma unroll
        for (int ks = 0; ks < 2; ks++) {
            ldsm_x4(qh[ks], qaddr + ks * 32);
            ldsm_x4(ql[ks], qaddr + ks * 32 + (FLM_QL - FLM_QH));
        }
    }

    float o[16][4];
#pragma unroll
    for (int d = 0; d < 16; d++)
#pragma unroll
        for (int f = 0; f < 4; f++) o[d][f] = 0.f;
    float m_i[2] = {NEG_INF, NEG_INF};
    float l_i[2] = {0.f, 0.f};

    for (int kt = 0; kt < N_ / 128; kt++) {
        const int k0 = kt * 128;
        __syncthreads();   // previous iteration's smem readers done

        // ---- load K tile (128x32) split hi/lo ----
        {
            const float* Kg = Kx + ((size_t)bh * N_ + k0) * R_;
#pragma unroll
            for (int v = 0; v < 4; v++) {
                int c = tid + v * 256;
                int r = c >> 3, q = c & 7;
                float4 f = *(const float4*)(Kg + (size_t)r * R_ + q * 4);
                __nv_bfloat16 h0, h1, h2, h3, l0, l1, l2, l3;
                split2(f.x, h0, l0); split2(f.y, h1, l1);
                split2(f.z, h2, l2); split2(f.w, h3, l3);
                uint32_t off = (uint32_t)(r * 80 + q * 8);
                *(uint2*)(sm + FLM_KH + off) = make_uint2(packbf(h0, h1), packbf(h2, h3));
                *(uint2*)(sm + FLM_KL + off) = make_uint2(packbf(l0, l1), packbf(l2, l3));
            }
        }
        // ---- load V tile (128x128) split hi/lo ----
        {
            const float* Vg = V + ((size_t)bh * N_ + k0) * DK_;
#pragma unroll
            for (int v = 0; v < 16; v++) {
                int c = tid + v * 256;
                int r = c >> 5, q = c & 31;
                float4 f = *(const float4*)(Vg + (size_t)r * DK_ + q * 4);
                __nv_bfloat16 h0, h1, h2, h3, l0, l1, l2, l3;
                split2(f.x, h0, l0); split2(f.y, h1, l1);
                split2(f.z, h2, l2); split2(f.w, h3, l3);
                uint32_t off = (uint32_t)(r * VSTR + q * 8);
                *(uint2*)(sm + FLM_VH + off) = make_uint2(packbf(h0, h1), packbf(h2, h3));
                *(uint2*)(sm + FLM_VL + off) = make_uint2(packbf(l0, l1), packbf(l2, l3));
            }
        }
        __syncthreads();

        // ---- S = Q K^T  (3x split) ----
        float s[16][4];
#pragma unroll
        for (int nb = 0; nb < 16; nb++)
#pragma unroll
            for (int f = 0; f < 4; f++) s[nb][f] = 0.f;

        {
            uint32_t baddr = sb + FLM_KH +
                (uint32_t)((lane & 7) * 40 + ((lane >> 3) & 1) * 8) * 2;
#pragma unroll
            for (int ks = 0; ks < 2; ks++) {
#pragma unroll
                for (int nb = 0; nb < 16; nb++) {
                    uint32_t bhh[2], bll[2];
                    uint32_t off = (uint32_t)(nb * 640 + ks * 32);
                    ldsm_x2(bhh, baddr + off);
                    ldsm_x2(bll, baddr + off + (FLM_KL - FLM_KH));
                    mma_bf16(s[nb], qh[ks], bhh);
                    mma_bf16(s[nb], qh[ks], bll);
                    mma_bf16(s[nb], ql[ks], bhh);
                }
            }
        }

        // ---- ALiBi bias + online softmax (in registers) ----
#pragma unroll
        for (int nb = 0; nb < 16; nb++) {
#pragma unroll
            for (int f = 0; f < 4; f++) {
                int r = f >> 1, c = f & 1;
                int jg = k0 + nb * 8 + t4 * 2 + c;
                int ig = q0 + wq * 16 + g + r * 8;
                float d = (float)(jg - ig);
                s[nb][f] -= slope * fmaxf(d, 0.f);
            }
        }

        float alpha[2], mnew[2];
#pragma unroll
        for (int r = 0; r < 2; r++) {
            float tm = NEG_INF;
#pragma unroll
            for (int nb = 0; nb < 16; nb++) {
                tm = fmaxf(tm, s[nb][r * 2]);
                tm = fmaxf(tm, s[nb][r * 2 + 1]);
            }
            tm = fmaxf(tm, __shfl_xor_sync(0xffffffffu, tm, 1));
            tm = fmaxf(tm, __shfl_xor_sync(0xffffffffu, tm, 2));
            mnew[r]  = fmaxf(m_i[r], tm);
            alpha[r] = __expf(m_i[r] - mnew[r]);
            m_i[r]   = mnew[r];
        }

        float rsum[2] = {0.f, 0.f};
#pragma unroll
        for (int nb = 0; nb < 16; nb++) {
#pragma unroll
            for (int f = 0; f < 4; f++) {
                int r = f >> 1;
                float p = __expf(s[nb][f] - mnew[r]);
                s[nb][f] = p;
                rsum[r] += p;
            }
        }
#pragma unroll
        for (int r = 0; r < 2; r++) {
            rsum[r] += __shfl_xor_sync(0xffffffffu, rsum[r], 1);
            rsum[r] += __shfl_xor_sync(0xffffffffu, rsum[r], 2);
            l_i[r] = l_i[r] * alpha[r] + rsum[r];
        }
#pragma unroll
        for (int d = 0; d < 16; d++)
#pragma unroll
            for (int f = 0; f < 4; f++) o[d][f] *= alpha[f >> 1];

        // ---- O += P V  (P packed reg->reg; V via ldmatrix.trans) ----
        {
            uint32_t vaddr = sb + FLM_VH +
                (uint32_t)((lane & 15) * VSTR + (lane >> 4) * 16);
#pragma unroll
            for (int ks = 0; ks < 8; ks++) {
                uint32_t aH[4], aL[4];
                pack_hilo(s[2 * ks][0],     s[2 * ks][1],     aH[0], aL[0]);
                pack_hilo(s[2 * ks][2],     s[2 * ks][3],     aH[1], aL[1]);
                pack_hilo(s[2 * ks + 1][0], s[2 * ks + 1][1], aH[2], aL[2]);
                pack_hilo(s[2 * ks + 1][2], s[2 * ks + 1][3], aH[3], aL[3]);
#pragma unroll
                for (int db = 0; db < 8; db++) {
                    uint32_t vh4[4], vl4[4];
                    uint32_t off = (uint32_t)(ks * 16 * VSTR + db * 32);
                    ldsm_x4_t(vh4, vaddr + off);
                    ldsm_x4_t(vl4, vaddr + off + (FLM_VL - FLM_VH));
                    mma_bf16(o[db * 2],     aH, vh4);
                    mma_bf16(o[db * 2],     aH, vl4);
                    mma_bf16(o[db * 2],     aL, vh4);
                    mma_bf16(o[db * 2 + 1], aH, vh4 + 2);
                    mma_bf16(o[db * 2 + 1], aH, vl4 + 2);
                    mma_bf16(o[db * 2 + 1], aL, vh4 + 2);
                }
            }
        }
    }

    // ---- finalize: Z[b, q, h*128+dk] = O / l ----
    float inv[2] = {1.f / l_i[0], 1.f / l_i[1]};
#pragma unroll
    for (int db = 0; db < 16; db++) {
#pragma unroll
        for (int r = 0; r < 2; r++) {
            int row = q0 + wq * 16 + g + r * 8;
            size_t zoff = ((size_t)b_ * N_ + row) * D_ + h * DK_ + db * 8 + t4 * 2;
            float2 val = make_float2(o[db][r * 2] * inv[r], o[db][r * 2 + 1] * inv[r]);
            *(float2*)(Z + zoff) = val;
        }
    }
}

// ---------------------------------------------------------------------------
// Host launcher (graph-capturable: kernel launches only)
// ---------------------------------------------------------------------------
extern "C" void kernel_launch(void* const* d_in, const int* in_sizes, int n_in,
                              void* d_out, int out_size)
{
    (void)in_sizes; (void)n_in; (void)out_size;
    const float* x     = (const float*)d_in[0];
    const float* Wq    = (const float*)d_in[1];
    const float* Wk    = (const float*)d_in[2];
    const float* Wv    = (const float*)d_in[3];
    const float* U     = (const float*)d_in[4];
    const float* Wproj = (const float*)d_in[5];
    float* out = (float*)d_out;

    float *WUq, *WUk, *Qp, *Kp, *Vp, *Zp;
    cudaGetSymbolAddress((void**)&WUq, g_WUq);
    cudaGetSymbolAddress((void**)&WUk, g_WUk);
    cudaGetSymbolAddress((void**)&Qp,  g_Q);
    cudaGetSymbolAddress((void**)&Kp,  g_K);
    cudaGetSymbolAddress((void**)&Vp,  g_V);
    cudaGetSymbolAddress((void**)&Zp,  g_Z);

    cudaFuncSetAttribute(flash_mma_kernel,
                         cudaFuncAttributeMaxDynamicSharedMemorySize, FLM_SMEM);

    // 0) fold U into Wq/Wk (fp32)
    build_wu_kernel<<<dim3(D_ / 256, HR_), 256>>>(Wq, U, WUq);
    build_wu_kernel<<<dim3(D_ / 256, HR_), 256>>>(Wk, U, WUk);

    // 1) Q = x @ WUq^T  -> [b,h,n,r]
    gemm_mma_bf16x3<1, R_><<<dim3(HR_ / 128, M_ / 128), 256, GM_SMEM>>>(
        x, WUq, Qp, HR_, D_);
    // 2) K = x @ WUk^T
    gemm_mma_bf16x3<1, R_><<<dim3(HR_ / 128, M_ / 128), 256, GM_SMEM>>>(
        x, WUk, Kp, HR_, D_);
    // 3) V = x @ Wv^T   -> [b,h,n,dk]
    gemm_mma_bf16x3<1, DK_><<<dim3(D_ / 128, M_ / 128), 256, GM_SMEM>>>(
        x, Wv, Vp, D_, D_);

    // 4) HMMA flash attention with ALiBi -> Z [b,n,d]
    flash_mma_kernel<<<dim3(N_ / 128, B_ * H_), 256, FLM_SMEM>>>(Qp, Kp, Vp, Zp);

    // 5) out = Z @ Wproj^T
    gemm_mma_bf16x3<0, 1><<<dim3(D_ / 128, M_ / 128), 256, GM_SMEM>>>(
        Zp, Wproj, out, D_, D_);
}

// round 9
// speedup vs baseline: 3.1410x; 1.0798x over previous
#include <cuda_runtime.h>
#include <cuda_bf16.h>
#include <math.h>
#include <stdint.h>

// ---------------------------------------------------------------------------
// Problem constants (B=4, N=2048, D=2048, H=16, DK=128, R=32)
// ---------------------------------------------------------------------------
#define B_   4
#define N_   2048
#define D_   2048
#define H_   16
#define DK_  128
#define R_   32
#define M_   (B_ * N_)      // 8192
#define HR_  (H_ * R_)      // 512

// ---------------------------------------------------------------------------
// Device scratch (bf16 hi/lo everywhere between stages)
// ---------------------------------------------------------------------------
__device__ __nv_bfloat16 g_xh [(size_t)M_ * D_];
__device__ __nv_bfloat16 g_xl [(size_t)M_ * D_];
__device__ __nv_bfloat16 g_WUqh[(size_t)HR_ * D_];
__device__ __nv_bfloat16 g_WUql[(size_t)HR_ * D_];
__device__ __nv_bfloat16 g_WUkh[(size_t)HR_ * D_];
__device__ __nv_bfloat16 g_WUkl[(size_t)HR_ * D_];
__device__ __nv_bfloat16 g_Wvh[(size_t)D_ * D_];
__device__ __nv_bfloat16 g_Wvl[(size_t)D_ * D_];
__device__ __nv_bfloat16 g_Wph[(size_t)D_ * D_];
__device__ __nv_bfloat16 g_Wpl[(size_t)D_ * D_];
__device__ __nv_bfloat16 g_Qh[(size_t)B_ * H_ * N_ * R_];
__device__ __nv_bfloat16 g_Ql[(size_t)B_ * H_ * N_ * R_];
__device__ __nv_bfloat16 g_Kh[(size_t)B_ * H_ * N_ * R_];
__device__ __nv_bfloat16 g_Kl[(size_t)B_ * H_ * N_ * R_];
__device__ __nv_bfloat16 g_Vh[(size_t)B_ * H_ * N_ * DK_];
__device__ __nv_bfloat16 g_Vl[(size_t)B_ * H_ * N_ * DK_];
__device__ __nv_bfloat16 g_Zh[(size_t)M_ * D_];
__device__ __nv_bfloat16 g_Zl[(size_t)M_ * D_];

// ---------------------------------------------------------------------------
// PTX wrappers (sm_80-era, valid on plain sm_103 target)
// ---------------------------------------------------------------------------
__device__ __forceinline__ uint32_t smem_u32(const void* p) {
    uint32_t a;
    asm("{ .reg .u64 t; cvta.to.shared.u64 t, %1; cvt.u32.u64 %0, t; }"
        : "=r"(a) : "l"(p));
    return a;
}
__device__ __forceinline__ void ldsm_x4(uint32_t* r, uint32_t addr) {
    asm volatile("ldmatrix.sync.aligned.m8n8.x4.shared.b16 {%0,%1,%2,%3}, [%4];"
                 : "=r"(r[0]), "=r"(r[1]), "=r"(r[2]), "=r"(r[3]) : "r"(addr));
}
__device__ __forceinline__ void ldsm_x2(uint32_t* r, uint32_t addr) {
    asm volatile("ldmatrix.sync.aligned.m8n8.x2.shared.b16 {%0,%1}, [%2];"
                 : "=r"(r[0]), "=r"(r[1]) : "r"(addr));
}
__device__ __forceinline__ void ldsm_x4_t(uint32_t* r, uint32_t addr) {
    asm volatile("ldmatrix.sync.aligned.m8n8.x4.trans.shared.b16 {%0,%1,%2,%3}, [%4];"
                 : "=r"(r[0]), "=r"(r[1]), "=r"(r[2]), "=r"(r[3]) : "r"(addr));
}
__device__ __forceinline__ void mma_bf16(float* d, const uint32_t* a, const uint32_t* b) {
    asm volatile(
        "mma.sync.aligned.m16n8k16.row.col.f32.bf16.bf16.f32 "
        "{%0,%1,%2,%3}, {%4,%5,%6,%7}, {%8,%9}, {%0,%1,%2,%3};"
        : "+f"(d[0]), "+f"(d[1]), "+f"(d[2]), "+f"(d[3])
        : "r"(a[0]), "r"(a[1]), "r"(a[2]), "r"(a[3]), "r"(b[0]), "r"(b[1]));
}
__device__ __forceinline__ void cp16(uint32_t dst, const void* src) {
    asm volatile("cp.async.cg.shared.global [%0], [%1], 16;"
                 :: "r"(dst), "l"(src) : "memory");
}
#define CP_COMMIT() asm volatile("cp.async.commit_group;" ::: "memory")
#define CP_WAIT1()  asm volatile("cp.async.wait_group 1;" ::: "memory")
#define CP_WAIT2()  asm volatile("cp.async.wait_group 2;" ::: "memory")

__device__ __forceinline__ void split2(float x, __nv_bfloat16& h, __nv_bfloat16& l) {
    h = __float2bfloat16(x);
    l = __float2bfloat16(x - __bfloat162float(h));
}
__device__ __forceinline__ uint32_t packbf(__nv_bfloat16 a, __nv_bfloat16 b) {
    return (uint32_t)__bfloat16_as_ushort(a) | ((uint32_t)__bfloat16_as_ushort(b) << 16);
}
__device__ __forceinline__ void pack_hilo(float x, float y, uint32_t& hi, uint32_t& lo) {
    __nv_bfloat16 hx, lx, hy, ly;
    split2(x, hx, lx); split2(y, hy, ly);
    hi = packbf(hx, hy); lo = packbf(lx, ly);
}

// ---------------------------------------------------------------------------
// Prep kernels
// ---------------------------------------------------------------------------
__global__ void split_bf16_kernel(const float4* __restrict__ in,
                                  uint2* __restrict__ hi, uint2* __restrict__ lo, int n4)
{
    int i = blockIdx.x * 256 + threadIdx.x;
    if (i >= n4) return;
    float4 v = in[i];
    __nv_bfloat16 h0, h1, h2, h3, l0, l1, l2, l3;
    split2(v.x, h0, l0); split2(v.y, h1, l1);
    split2(v.z, h2, l2); split2(v.w, h3, l3);
    hi[i] = make_uint2(packbf(h0, h1), packbf(h2, h3));
    lo[i] = make_uint2(packbf(l0, l1), packbf(l2, l3));
}

__global__ void build_wu_kernel(const float* __restrict__ W,
                                const float* __restrict__ U,
                                __nv_bfloat16* __restrict__ WUh,
                                __nv_bfloat16* __restrict__ WUl)
{
    int d  = blockIdx.x * 256 + threadIdx.x;
    int hr = blockIdx.y;
    int h  = hr >> 5;
    int r  = hr & 31;
    const float* wcol = W + (size_t)h * DK_ * D_ + d;
    float s = 0.f;
#pragma unroll 8
    for (int dk = 0; dk < DK_; dk++)
        s += wcol[(size_t)dk * D_] * U[dk * R_ + r];
    __nv_bfloat16 hh, ll;
    split2(s, hh, ll);
    WUh[(size_t)hr * D_ + d] = hh;
    WUl[(size_t)hr * D_ + d] = ll;
}

// ---------------------------------------------------------------------------
// HMMA 3xBF16 GEMM on pre-split inputs, cp.async double-buffered.
//   C[m,n] = sum_k A[m,k]*B[n,k];  K in bf16 elements (K-major rows).
// CTA 128x128, BK=32, 8 warps (2x4), warp tile 64x32.
// smem/stage: Ah|Al|Bh|Bl each 128 rows x 80 B (64 B data) = 40960 B; 2 stages.
// MODE 0: fp32 C[m*NN+n]
// MODE 1: bf16 hi/lo head-split: Ch/Cl[((b*H + n/SPLIT)*N + m%N)*SPLIT + n%SPLIT],
//         value scaled by `scale` before split.
// ---------------------------------------------------------------------------
#define SG_SIZE 40960
#define GEMM_SMEM (2 * SG_SIZE)

template <int MODE, int SPLIT>
__global__ void __launch_bounds__(256, 2)
gemm_cp_bf16x3(const __nv_bfloat16* __restrict__ Ah,
               const __nv_bfloat16* __restrict__ Al,
               const __nv_bfloat16* __restrict__ Bh,
               const __nv_bfloat16* __restrict__ Bl,
               float* __restrict__ Cf,
               __nv_bfloat16* __restrict__ Ch,
               __nv_bfloat16* __restrict__ Cl,
               int NN, int K, float scale)
{
    extern __shared__ char sm[];
    const uint32_t sb = smem_u32(sm);

    const int tid  = threadIdx.x;
    const int lane = tid & 31;
    const int wid  = tid >> 5;
    const int wm   = wid & 1;
    const int wn   = wid >> 1;
    const int m0   = blockIdx.y * 128;
    const int n0   = blockIdx.x * 128;

    const __nv_bfloat16* srcs[4] = {
        Ah + (size_t)m0 * K, Al + (size_t)m0 * K,
        Bh + (size_t)n0 * K, Bl + (size_t)n0 * K };

    // issue loads for iteration `it` into stage `st` (compile-time-unrolled v)
    auto issue = [&](int st, int it) {
#pragma unroll
        for (int v = 0; v < 8; v++) {
            const int buf = v >> 1;
            int idx = (v & 1) * 256 + tid;    // 0..511
            int row = idx >> 2, q = idx & 3;
            const __nv_bfloat16* src = srcs[buf] + (size_t)row * K + it * 32 + q * 8;
            uint32_t dst = sb + st * SG_SIZE + buf * 10240 + (uint32_t)(row * 80 + q * 16);
            cp16(dst, src);
        }
    };

    const int niter = K / 32;
    issue(0, 0); CP_COMMIT();
    issue(1, 1); CP_COMMIT();

    float acc[4][4][4];
#pragma unroll
    for (int mi = 0; mi < 4; mi++)
#pragma unroll
        for (int ni = 0; ni < 4; ni++)
#pragma unroll
            for (int f = 0; f < 4; f++) acc[mi][ni][f] = 0.f;

    const uint32_t a_off =
        (uint32_t)((wm * 64 + (lane & 15)) * 40 + ((lane >> 4) * 8)) * 2;
    const uint32_t b_off = 20480u +
        (uint32_t)((wn * 32 + (lane & 7)) * 40 + (((lane >> 3) & 1) * 8)) * 2;

    for (int it = 0; it < niter; ++it) {
        CP_WAIT1();
        __syncthreads();
        const uint32_t stb = sb + (uint32_t)(it & 1) * SG_SIZE;
        const uint32_t a_addr = stb + a_off;
        const uint32_t b_addr = stb + b_off;

#pragma unroll
        for (int ks = 0; ks < 2; ks++) {
            uint32_t ah[4][4], al[4][4];
#pragma unroll
            for (int mi = 0; mi < 4; mi++) {
                uint32_t off = (uint32_t)(mi * 1280 + ks * 32);
                ldsm_x4(ah[mi], a_addr + off);
                ldsm_x4(al[mi], a_addr + off + 10240);
            }
#pragma unroll
            for (int ni = 0; ni < 4; ni++) {
                uint32_t bh[2], bl[2];
                uint32_t off = (uint32_t)(ni * 640 + ks * 32);
                ldsm_x2(bh, b_addr + off);
                ldsm_x2(bl, b_addr + off + 10240);
#pragma unroll
                for (int mi = 0; mi < 4; mi++) {
                    mma_bf16(acc[mi][ni], ah[mi], bh);
                    mma_bf16(acc[mi][ni], ah[mi], bl);
                    mma_bf16(acc[mi][ni], al[mi], bh);
                }
            }
        }
        __syncthreads();
        if (it + 2 < niter) { issue(it & 1, it + 2); CP_COMMIT(); }
    }

    // epilogue
    const int g  = lane >> 2;
    const int c2 = (lane & 3) * 2;
#pragma unroll
    for (int mi = 0; mi < 4; mi++) {
#pragma unroll
        for (int ni = 0; ni < 4; ni++) {
            int m = m0 + wm * 64 + mi * 16 + g;
            int n = n0 + wn * 32 + ni * 8 + c2;
#pragma unroll
            for (int half = 0; half < 2; half++) {
                int mm = m + half * 8;
                float v0 = acc[mi][ni][half * 2];
                float v1 = acc[mi][ni][half * 2 + 1];
                if (MODE == 0) {
                    *(float2*)(Cf + (size_t)mm * NN + n) = make_float2(v0, v1);
                } else {
                    int b_ = mm >> 11;
                    int t  = mm & (N_ - 1);
                    int h  = n / SPLIT;
                    int j  = n % SPLIT;
                    size_t off = (((size_t)(b_ * H_ + h)) * N_ + t) * SPLIT + j;
                    uint32_t hi, lo;
                    pack_hilo(v0 * scale, v1 * scale, hi, lo);
                    *(uint32_t*)(Ch + off) = hi;
                    *(uint32_t*)(Cl + off) = lo;
                }
            }
        }
    }
}

// ---------------------------------------------------------------------------
// HMMA flash attention, pre-split bf16 inputs, cp.async double-buffered K/V.
//   CTA: 128 q-rows, 8 warps (16 q-rows each), 16 key tiles of 128.
// smem: Q hi/lo 2x10240 | K stages 2x(10240+10240) | V stages 2x(34816+34816)
// ---------------------------------------------------------------------------
#define FQ_H 0
#define FQ_L 10240
#define FK_BASE 20480
#define FK_STAGE 20480
#define FV_BASE 61440
#define FV_STAGE 69632
#define FLM_SMEM 200704
#define VSTR 272

__global__ void __launch_bounds__(256, 1)
flash_cp_kernel(const __nv_bfloat16* __restrict__ Qh, const __nv_bfloat16* __restrict__ Ql,
                const __nv_bfloat16* __restrict__ Kh, const __nv_bfloat16* __restrict__ Kl,
                const __nv_bfloat16* __restrict__ Vh, const __nv_bfloat16* __restrict__ Vl,
                __nv_bfloat16* __restrict__ Zh, __nv_bfloat16* __restrict__ Zl)
{
    extern __shared__ char sm[];
    const uint32_t sb = smem_u32(sm);

    const int tid  = threadIdx.x;
    const int lane = tid & 31;
    const int wq   = tid >> 5;
    const int bh   = blockIdx.y;
    const int h    = bh & (H_ - 1);
    const int b_   = bh >> 4;
    const int q0   = blockIdx.x * 128;
    const int g    = lane >> 2;
    const int t4   = lane & 3;

    const float slope = exp2f(-0.5f * (float)(h + 1));
    const float NEG_INF = -__int_as_float(0x7f800000);

    // issue K+V stage loads for key tile kt2 into stage st
    auto issue_kv = [&](int st, int kt2) {
        const int k0 = kt2 * 128;
        const __nv_bfloat16* kh = Kh + ((size_t)bh * N_ + k0) * R_;
        const __nv_bfloat16* kl = Kl + ((size_t)bh * N_ + k0) * R_;
#pragma unroll
        for (int v = 0; v < 4; v++) {
            int idx = (v & 1) * 256 + tid;
            int row = idx >> 2, q = idx & 3;
            const __nv_bfloat16* src = (v < 2 ? kh : kl) + (size_t)row * R_ + q * 8;
            uint32_t dst = sb + FK_BASE + st * FK_STAGE + (v < 2 ? 0 : 10240)
                         + (uint32_t)(row * 80 + q * 16);
            cp16(dst, src);
        }
        const __nv_bfloat16* vh = Vh + ((size_t)bh * N_ + k0) * DK_;
        const __nv_bfloat16* vl = Vl + ((size_t)bh * N_ + k0) * DK_;
#pragma unroll
        for (int v = 0; v < 16; v++) {
            int idx = (v & 7) * 256 + tid;
            int row = idx >> 4, q = idx & 15;
            const __nv_bfloat16* src = (v < 8 ? vh : vl) + (size_t)row * DK_ + q * 8;
            uint32_t dst = sb + FV_BASE + st * FV_STAGE + (v < 8 ? 0 : 34816)
                         + (uint32_t)(row * VSTR + q * 16);
            cp16(dst, src);
        }
    };

    // Q load (one-time)
    {
        const __nv_bfloat16* qh_ = Qh + ((size_t)bh * N_ + q0) * R_;
        const __nv_bfloat16* ql_ = Ql + ((size_t)bh * N_ + q0) * R_;
#pragma unroll
        for (int v = 0; v < 4; v++) {
            int idx = (v & 1) * 256 + tid;
            int row = idx >> 2, q = idx & 3;
            const __nv_bfloat16* src = (v < 2 ? qh_ : ql_) + (size_t)row * R_ + q * 8;
            uint32_t dst = sb + (v < 2 ? FQ_H : FQ_L) + (uint32_t)(row * 80 + q * 16);
            cp16(dst, src);
        }
    }
    CP_COMMIT();
    issue_kv(0, 0); CP_COMMIT();
    issue_kv(1, 1); CP_COMMIT();

    CP_WAIT2();            // Q ready
    __syncthreads();

    uint32_t qh[2][4], ql[2][4];
    {
        uint32_t qaddr = sb + FQ_H +
            (uint32_t)((wq * 16 + (lane & 15)) * 40 + (lane >> 4) * 8) * 2;
#pragma unroll
        for (int ks = 0; ks < 2; ks++) {
            ldsm_x4(qh[ks], qaddr + ks * 32);
            ldsm_x4(ql[ks], qaddr + ks * 32 + 10240);
        }
    }

    float o[16][4];
#pragma unroll
    for (int d = 0; d < 16; d++)
#pragma unroll
        for (int f = 0; f < 4; f++) o[d][f] = 0.f;
    float m_i[2] = {NEG_INF, NEG_INF};
    float l_i[2] = {0.f, 0.f};

    for (int kt = 0; kt < N_ / 128; kt++) {
        const int k0 = kt * 128;
        CP_WAIT1();
        __syncthreads();
        const int st = kt & 1;

        // ---- S = Q K^T (3x split) ----
        float s[16][4];
#pragma unroll
        for (int nb = 0; nb < 16; nb++)
#pragma unroll
            for (int f = 0; f < 4; f++) s[nb][f] = 0.f;

        {
            uint32_t baddr = sb + FK_BASE + st * FK_STAGE +
                (uint32_t)((lane & 7) * 40 + ((lane >> 3) & 1) * 8) * 2;
#pragma unroll
            for (int ks = 0; ks < 2; ks++) {
#pragma unroll
                for (int nb = 0; nb < 16; nb++) {
                    uint32_t bhh[2], bll[2];
                    uint32_t off = (uint32_t)(nb * 640 + ks * 32);
                    ldsm_x2(bhh, baddr + off);
                    ldsm_x2(bll, baddr + off + 10240);
                    mma_bf16(s[nb], qh[ks], bhh);
                    mma_bf16(s[nb], qh[ks], bll);
                    mma_bf16(s[nb], ql[ks], bhh);
                }
            }
        }

        // ---- ALiBi + online softmax (registers) ----
#pragma unroll
        for (int nb = 0; nb < 16; nb++) {
#pragma unroll
            for (int f = 0; f < 4; f++) {
                int r = f >> 1, c = f & 1;
                int jg = k0 + nb * 8 + t4 * 2 + c;
                int ig = q0 + wq * 16 + g + r * 8;
                s[nb][f] -= slope * fmaxf((float)(jg - ig), 0.f);
            }
        }

        float alpha[2], mnew[2];
#pragma unroll
        for (int r = 0; r < 2; r++) {
            float tm = NEG_INF;
#pragma unroll
            for (int nb = 0; nb < 16; nb++) {
                tm = fmaxf(tm, s[nb][r * 2]);
                tm = fmaxf(tm, s[nb][r * 2 + 1]);
            }
            tm = fmaxf(tm, __shfl_xor_sync(0xffffffffu, tm, 1));
            tm = fmaxf(tm, __shfl_xor_sync(0xffffffffu, tm, 2));
            mnew[r]  = fmaxf(m_i[r], tm);
            alpha[r] = __expf(m_i[r] - mnew[r]);
            m_i[r]   = mnew[r];
        }

        float rsum[2] = {0.f, 0.f};
#pragma unroll
        for (int nb = 0; nb < 16; nb++) {
#pragma unroll
            for (int f = 0; f < 4; f++) {
                int r = f >> 1;
                float p = __expf(s[nb][f] - mnew[r]);
                s[nb][f] = p;
                rsum[r] += p;
            }
        }
#pragma unroll
        for (int r = 0; r < 2; r++) {
            rsum[r] += __shfl_xor_sync(0xffffffffu, rsum[r], 1);
            rsum[r] += __shfl_xor_sync(0xffffffffu, rsum[r], 2);
            l_i[r] = l_i[r] * alpha[r] + rsum[r];
        }
#pragma unroll
        for (int d = 0; d < 16; d++)
#pragma unroll
            for (int f = 0; f < 4; f++) o[d][f] *= alpha[f >> 1];

        // ---- O += P V (P packed reg->reg; V via ldmatrix.trans) ----
        {
            uint32_t vaddr = sb + FV_BASE + st * FV_STAGE +
                (uint32_t)((lane & 15) * VSTR + (lane >> 4) * 16);
#pragma unroll
            for (int ks = 0; ks < 8; ks++) {
                uint32_t aH[4], aL[4];
                pack_hilo(s[2 * ks][0],     s[2 * ks][1],     aH[0], aL[0]);
                pack_hilo(s[2 * ks][2],     s[2 * ks][3],     aH[1], aL[1]);
                pack_hilo(s[2 * ks + 1][0], s[2 * ks + 1][1], aH[2], aL[2]);
                pack_hilo(s[2 * ks + 1][2], s[2 * ks + 1][3], aH[3], aL[3]);
#pragma unroll
                for (int db = 0; db < 8; db++) {
                    uint32_t vh4[4], vl4[4];
                    uint32_t off = (uint32_t)(ks * 16 * VSTR + db * 32);
                    ldsm_x4_t(vh4, vaddr + off);
                    ldsm_x4_t(vl4, vaddr + off + 34816);
                    mma_bf16(o[db * 2],     aH, vh4);
                    mma_bf16(o[db * 2],     aH, vl4);
                    mma_bf16(o[db * 2],     aL, vh4);
                    mma_bf16(o[db * 2 + 1], aH, vh4 + 2);
                    mma_bf16(o[db * 2 + 1], aH, vl4 + 2);
                    mma_bf16(o[db * 2 + 1], aL, vh4 + 2);
                }
            }
        }
        __syncthreads();
        if (kt + 2 < N_ / 128) { issue_kv(st, kt + 2); CP_COMMIT(); }
    }

    // ---- finalize: Z (bf16 hi/lo) = O / l ----
    float inv[2] = {1.f / l_i[0], 1.f / l_i[1]};
#pragma unroll
    for (int db = 0; db < 16; db++) {
#pragma unroll
        for (int r = 0; r < 2; r++) {
            int row = q0 + wq * 16 + g + r * 8;
            size_t zoff = ((size_t)b_ * N_ + row) * D_ + h * DK_ + db * 8 + t4 * 2;
            uint32_t hi, lo;
            pack_hilo(o[db][r * 2] * inv[r], o[db][r * 2 + 1] * inv[r], hi, lo);
            *(uint32_t*)(Zh + zoff) = hi;
            *(uint32_t*)(Zl + zoff) = lo;
        }
    }
}

// ---------------------------------------------------------------------------
// Host launcher (graph-capturable: kernel launches only)
// ---------------------------------------------------------------------------
extern "C" void kernel_launch(void* const* d_in, const int* in_sizes, int n_in,
                              void* d_out, int out_size)
{
    (void)in_sizes; (void)n_in; (void)out_size;
    const float* x     = (const float*)d_in[0];
    const float* Wq    = (const float*)d_in[1];
    const float* Wk    = (const float*)d_in[2];
    const float* Wv    = (const float*)d_in[3];
    const float* U     = (const float*)d_in[4];
    const float* Wproj = (const float*)d_in[5];
    float* out = (float*)d_out;

    __nv_bfloat16 *xh, *xl, *WUqh, *WUql, *WUkh, *WUkl, *Wvh, *Wvl, *Wph, *Wpl;
    __nv_bfloat16 *Qh, *Ql, *Kh, *Kl, *Vh, *Vl, *Zh, *Zl;
    cudaGetSymbolAddress((void**)&xh,   g_xh);
    cudaGetSymbolAddress((void**)&xl,   g_xl);
    cudaGetSymbolAddress((void**)&WUqh, g_WUqh);
    cudaGetSymbolAddress((void**)&WUql, g_WUql);
    cudaGetSymbolAddress((void**)&WUkh, g_WUkh);
    cudaGetSymbolAddress((void**)&WUkl, g_WUkl);
    cudaGetSymbolAddress((void**)&Wvh,  g_Wvh);
    cudaGetSymbolAddress((void**)&Wvl,  g_Wvl);
    cudaGetSymbolAddress((void**)&Wph,  g_Wph);
    cudaGetSymbolAddress((void**)&Wpl,  g_Wpl);
    cudaGetSymbolAddress((void**)&Qh,   g_Qh);
    cudaGetSymbolAddress((void**)&Ql,   g_Ql);
    cudaGetSymbolAddress((void**)&Kh,   g_Kh);
    cudaGetSymbolAddress((void**)&Kl,   g_Kl);
    cudaGetSymbolAddress((void**)&Vh,   g_Vh);
    cudaGetSymbolAddress((void**)&Vl,   g_Vl);
    cudaGetSymbolAddress((void**)&Zh,   g_Zh);
    cudaGetSymbolAddress((void**)&Zl,   g_Zl);

    cudaFuncSetAttribute(gemm_cp_bf16x3<1, R_>,
                         cudaFuncAttributeMaxDynamicSharedMemorySize, GEMM_SMEM);
    cudaFuncSetAttribute(gemm_cp_bf16x3<1, DK_>,
                         cudaFuncAttributeMaxDynamicSharedMemorySize, GEMM_SMEM);
    cudaFuncSetAttribute(gemm_cp_bf16x3<0, 1>,
                         cudaFuncAttributeMaxDynamicSharedMemorySize, GEMM_SMEM);
    cudaFuncSetAttribute(flash_cp_kernel,
                         cudaFuncAttributeMaxDynamicSharedMemorySize, FLM_SMEM);

    const float qscale = rsqrtf((float)DK_);

    // 0) one-time splits + U-folding
    split_bf16_kernel<<<(M_ * D_ / 4) / 256, 256>>>(
        (const float4*)x, (uint2*)xh, (uint2*)xl, M_ * D_ / 4);
    split_bf16_kernel<<<(D_ * D_ / 4) / 256, 256>>>(
        (const float4*)Wv, (uint2*)Wvh, (uint2*)Wvl, D_ * D_ / 4);
    split_bf16_kernel<<<(D_ * D_ / 4) / 256, 256>>>(
        (const float4*)Wproj, (uint2*)Wph, (uint2*)Wpl, D_ * D_ / 4);
    build_wu_kernel<<<dim3(D_ / 256, HR_), 256>>>(Wq, U, WUqh, WUql);
    build_wu_kernel<<<dim3(D_ / 256, HR_), 256>>>(Wk, U, WUkh, WUkl);

    // 1) Q = (x @ WUq^T) * 1/sqrt(dk) -> bf16 hi/lo [b,h,n,r]
    gemm_cp_bf16x3<1, R_><<<dim3(HR_ / 128, M_ / 128), 256, GEMM_SMEM>>>(
        xh, xl, WUqh, WUql, nullptr, Qh, Ql, HR_, D_, qscale);
    // 2) K = x @ WUk^T -> bf16 hi/lo
    gemm_cp_bf16x3<1, R_><<<dim3(HR_ / 128, M_ / 128), 256, GEMM_SMEM>>>(
        xh, xl, WUkh, WUkl, nullptr, Kh, Kl, HR_, D_, 1.0f);
    // 3) V = x @ Wv^T -> bf16 hi/lo [b,h,n,dk]
    gemm_cp_bf16x3<1, DK_><<<dim3(D_ / 128, M_ / 128), 256, GEMM_SMEM>>>(
        xh, xl, Wvh, Wvl, nullptr, Vh, Vl, D_, D_, 1.0f);

    // 4) flash attention with ALiBi -> Z bf16 hi/lo [b,n,d]
    flash_cp_kernel<<<dim3(N_ / 128, B_ * H_), 256, FLM_SMEM>>>(
        Qh, Ql, Kh, Kl, Vh, Vl, Zh, Zl);

    // 5) out = Z @ Wproj^T -> fp32
    gemm_cp_bf16x3<0, 1><<<dim3(D_ / 128, M_ / 128), 256, GEMM_SMEM>>>(
        Zh, Zl, Wph, Wpl, out, nullptr, nullptr, D_, D_, 1.0f);
}